// round 7
// baseline (speedup 1.0000x reference)
#include <cuda_runtime.h>
#include <cuda_bf16.h>
#include <cstdint>
#include <math.h>

#define BB 2
#define SS 2048
#define HH 32
#define HD 64
#define MD 2048
#define MTOT (BB*SS)

// ---------------- device scratch (static, no allocation) ----------------
__device__ __nv_bfloat16 gx_h[MTOT*MD],  gx_l[MTOT*MD];
__device__ __nv_bfloat16 gwq_h[MD*MD],   gwq_l[MD*MD];
__device__ __nv_bfloat16 gwk_h[MD*MD],   gwk_l[MD*MD];
__device__ __nv_bfloat16 gwv_h[MD*MD],   gwv_l[MD*MD];
__device__ __nv_bfloat16 gwo_h[MD*MD],   gwo_l[MD*MD];
__device__ __nv_bfloat16 gq_h[MTOT*MD],  gq_l[MTOT*MD];   // [bh][s][64]
__device__ __nv_bfloat16 gk_h[MTOT*MD],  gk_l[MTOT*MD];
__device__ __nv_bfloat16 gv_h[MTOT*MD],  gv_l[MTOT*MD];
__device__ __nv_bfloat16 gc_h[MTOT*MD],  gc_l[MTOT*MD];   // ctx [b*S+s][2048]
__device__ float g_biastab[HH*4096];

// ---------------- small helpers ----------------
__device__ __forceinline__ uint32_t smem_to_u32(const void* p) {
    uint32_t a;
    asm("{ .reg .u64 t; cvta.to.shared.u64 t, %1; cvt.u32.u64 %0, t; }" : "=r"(a) : "l"(p));
    return a;
}
__device__ __forceinline__ void cp16(uint32_t dst, const void* src) {
    asm volatile("cp.async.cg.shared.global [%0], [%1], 16;" :: "r"(dst), "l"(src));
}
__device__ __forceinline__ void cp4(uint32_t dst, const void* src) {
    asm volatile("cp.async.ca.shared.global [%0], [%1], 4;" :: "r"(dst), "l"(src));
}
#define CP_COMMIT() asm volatile("cp.async.commit_group;" ::: "memory")
#define CP_WAIT(n)  asm volatile("cp.async.wait_group %0;" :: "n"(n) : "memory")

__device__ __forceinline__ void ldx4(uint32_t* r, uint32_t addr) {
    asm volatile("ldmatrix.sync.aligned.m8n8.x4.shared.b16 {%0,%1,%2,%3}, [%4];"
                 : "=r"(r[0]), "=r"(r[1]), "=r"(r[2]), "=r"(r[3]) : "r"(addr));
}
__device__ __forceinline__ void ldx4t(uint32_t* r, uint32_t addr) {
    asm volatile("ldmatrix.sync.aligned.m8n8.x4.trans.shared.b16 {%0,%1,%2,%3}, [%4];"
                 : "=r"(r[0]), "=r"(r[1]), "=r"(r[2]), "=r"(r[3]) : "r"(addr));
}
__device__ __forceinline__ void mma_bf16(float* d, const uint32_t* a,
                                         uint32_t b0, uint32_t b1) {
    asm volatile(
        "mma.sync.aligned.m16n8k16.row.col.f32.bf16.bf16.f32 "
        "{%0,%1,%2,%3}, {%4,%5,%6,%7}, {%8,%9}, {%0,%1,%2,%3};"
        : "+f"(d[0]), "+f"(d[1]), "+f"(d[2]), "+f"(d[3])
        : "r"(a[0]), "r"(a[1]), "r"(a[2]), "r"(a[3]), "r"(b0), "r"(b1));
}

__device__ __forceinline__ uint32_t pack_hi(float a, float b) {
    return __byte_perm(__float_as_uint(a), __float_as_uint(b), 0x7632);
}
__device__ __forceinline__ uint32_t pack_lo_res(float a, float b) {
    float ra = a - __uint_as_float(__float_as_uint(a) & 0xffff0000u);
    float rb = b - __uint_as_float(__float_as_uint(b) & 0xffff0000u);
    uint32_t r;
    asm("cvt.rn.bf16x2.f32 %0, %1, %2;" : "=r"(r) : "f"(rb), "f"(ra));
    return r;
}

// fp32 -> bf16 hi/lo split (one-shot elementwise)
__global__ void convert_kernel(const float* __restrict__ in,
                               __nv_bfloat16* __restrict__ hi,
                               __nv_bfloat16* __restrict__ lo, int n4) {
    int i = blockIdx.x * blockDim.x + threadIdx.x;
    if (i >= n4) return;
    float4 f = reinterpret_cast<const float4*>(in)[i];
    reinterpret_cast<uint2*>(hi)[i] = make_uint2(pack_hi(f.x, f.y), pack_hi(f.z, f.w));
    reinterpret_cast<uint2*>(lo)[i] = make_uint2(pack_lo_res(f.x, f.y), pack_lo_res(f.z, f.w));
}

// 512-thread GEMM loader: thread t = (row t>>2, quarter t&3), 2x16B per buffer
__device__ __forceinline__ void issue4w(uint32_t sb,
    const __nv_bfloat16* s0, const __nv_bfloat16* s1,
    const __nv_bfloat16* s2, const __nv_bfloat16* s3, int tid)
{
    const int r4 = tid >> 2, qf = tid & 3;
    const uint32_t dd = (uint32_t)(r4 * 128 + qf * 32);
    #pragma unroll
    for (int i = 0; i < 2; i++) {
        uint32_t o = dd + i * 16; o ^= (o >> 3) & 0x70;
        cp16(sb + o,         s0 + i * 8);
        cp16(sb + 16384 + o, s1 + i * 8);
        cp16(sb + 32768 + o, s2 + i * 8);
        cp16(sb + 49152 + o, s3 + i * 8);
    }
}

// ===========================================================================
// bf16x3 GEMM: 512 threads, 16 warps (4m x 4n), warp tile 32x32.
// C[4096,2048] = A @ B^T. 128x128 CTA tile, chunk 64, 3 buffers, issue c+2.
// PERM=true: write bf16 hi/lo into [b,h,s,d] arrays. else fp32 plain C.
// ===========================================================================
#define GSMEM_BYTES (3 * 65536)

template<bool PERM>
__global__ void __launch_bounds__(512, 1) gemm3(
    const __nv_bfloat16* __restrict__ Ah, const __nv_bfloat16* __restrict__ Al,
    const __nv_bfloat16* __restrict__ Bh, const __nv_bfloat16* __restrict__ Bl,
    float* __restrict__ Cf,
    __nv_bfloat16* __restrict__ Ch, __nv_bfloat16* __restrict__ Cl)
{
    extern __shared__ char smem[];
    const uint32_t su = smem_to_u32(smem);
    const int tid = threadIdx.x;
    const int l = tid & 31, w = tid >> 5;
    const int wm = w >> 2, wn = w & 3;         // 4x4 warp grid, 32x32 tiles
    const int grp = l >> 3, lr = l & 7;
    const int m0 = (blockIdx.x >> 4) * 128, n0 = (blockIdx.x & 15) * 128;
    const int r4 = tid >> 2, qf = tid & 3;

    const __nv_bfloat16* pa_h = Ah + (size_t)(m0 + r4) * 2048 + qf * 16;
    const __nv_bfloat16* pa_l = Al + (size_t)(m0 + r4) * 2048 + qf * 16;
    const __nv_bfloat16* pb_h = Bh + (size_t)(n0 + r4) * 2048 + qf * 16;
    const __nv_bfloat16* pb_l = Bl + (size_t)(n0 + r4) * 2048 + qf * 16;

    issue4w(su,         pa_h,      pa_l,      pb_h,      pb_l,      tid); CP_COMMIT();
    issue4w(su + 65536, pa_h + 64, pa_l + 64, pb_h + 64, pb_l + 64, tid); CP_COMMIT();

    float acc[2][4][4];
    #pragma unroll
    for (int mt = 0; mt < 2; mt++)
        #pragma unroll
        for (int nt = 0; nt < 4; nt++)
            #pragma unroll
            for (int i = 0; i < 4; i++) acc[mt][nt][i] = 0.f;

    uint32_t a_row[2], b_row[2];
    #pragma unroll
    for (int mt = 0; mt < 2; mt++)
        a_row[mt] = (uint32_t)((wm * 32 + mt * 16 + lr + (grp & 1) * 8) * 128);
    #pragma unroll
    for (int j = 0; j < 2; j++)
        b_row[j] = (uint32_t)((wn * 32 + j * 16 + lr + (grp >> 1) * 8) * 128);
    const uint32_t a_c16 = (uint32_t)(grp >> 1) * 16;
    const uint32_t b_c16 = (uint32_t)(grp & 1) * 16;

    for (int c = 0; c < 32; c++) {
        CP_WAIT(1);
        __syncthreads();
        if (c + 2 < 32) {
            int k0 = (c + 2) * 64;
            issue4w(su + (uint32_t)((c + 2) % 3) * 65536,
                    pa_h + k0, pa_l + k0, pb_h + k0, pb_l + k0, tid);
        }
        CP_COMMIT();

        const uint32_t cur = su + (uint32_t)(c % 3) * 65536;
        const uint32_t uAh = cur, uAl = cur + 16384,
                       uBh = cur + 32768, uBl = cur + 49152;

        #pragma unroll
        for (int ks = 0; ks < 4; ks++) {
            uint32_t ah[2][4], al[2][4];
            #pragma unroll
            for (int mt = 0; mt < 2; mt++) {
                uint32_t off = a_row[mt] + (uint32_t)(ks * 32) + a_c16;
                off ^= (off >> 3) & 0x70;
                ldx4(ah[mt], uAh + off);
                ldx4(al[mt], uAl + off);
            }
            uint32_t bh[2][4], bl[2][4];
            #pragma unroll
            for (int j = 0; j < 2; j++) {
                uint32_t off = b_row[j] + (uint32_t)(ks * 32) + b_c16;
                off ^= (off >> 3) & 0x70;
                ldx4(bh[j], uBh + off);
                ldx4(bl[j], uBl + off);
            }
            #pragma unroll
            for (int mt = 0; mt < 2; mt++) {
                #pragma unroll
                for (int j = 0; j < 2; j++) {
                    mma_bf16(acc[mt][2*j],   ah[mt], bh[j][0], bh[j][1]);
                    mma_bf16(acc[mt][2*j],   ah[mt], bl[j][0], bl[j][1]);
                    mma_bf16(acc[mt][2*j],   al[mt], bh[j][0], bh[j][1]);
                    mma_bf16(acc[mt][2*j+1], ah[mt], bh[j][2], bh[j][3]);
                    mma_bf16(acc[mt][2*j+1], ah[mt], bl[j][2], bl[j][3]);
                    mma_bf16(acc[mt][2*j+1], al[mt], bh[j][2], bh[j][3]);
                }
            }
        }
    }

    // epilogue
    #pragma unroll
    for (int mt = 0; mt < 2; mt++) {
        #pragma unroll
        for (int nt = 0; nt < 4; nt++) {
            int r  = m0 + wm * 32 + mt * 16 + (l >> 2);
            int cc = n0 + wn * 32 + nt * 8 + 2 * (l & 3);
            if (PERM) {
                int b = r >> 11, s = r & 2047, h = cc >> 6, d = cc & 63;
                size_t base = (((size_t)(b * 32 + h)) * 2048 + s) * 64 + d;
                *reinterpret_cast<uint32_t*>(Ch + base) =
                    pack_hi(acc[mt][nt][0], acc[mt][nt][1]);
                *reinterpret_cast<uint32_t*>(Cl + base) =
                    pack_lo_res(acc[mt][nt][0], acc[mt][nt][1]);
                *reinterpret_cast<uint32_t*>(Ch + base + 8 * 64) =
                    pack_hi(acc[mt][nt][2], acc[mt][nt][3]);
                *reinterpret_cast<uint32_t*>(Cl + base + 8 * 64) =
                    pack_lo_res(acc[mt][nt][2], acc[mt][nt][3]);
            } else {
                *reinterpret_cast<float2*>(Cf + (size_t)r * 2048 + cc) =
                    make_float2(acc[mt][nt][0], acc[mt][nt][1]);
                *reinterpret_cast<float2*>(Cf + (size_t)(r + 8) * 2048 + cc) =
                    make_float2(acc[mt][nt][2], acc[mt][nt][3]);
            }
        }
    }
}

// ===========================================================================
// relative-position bucket (exact integer T5 formula) + bias table
// ===========================================================================
__device__ __forceinline__ int rel_bucket(int dist) {
    int rel = dist > 0 ? 16 : 0;
    int d = abs(dist);
    int sb;
    if (d < 8)       sb = d;
    else if (d < 12) sb = 8;
    else if (d < 16) sb = 9;
    else if (d < 23) sb = 10;
    else if (d < 32) sb = 11;
    else if (d < 46) sb = 12;
    else if (d < 64) sb = 13;
    else if (d < 91) sb = 14;
    else             sb = 15;
    return rel + sb;
}

__global__ void bias_table_kernel(const float* __restrict__ rel_bias) {
    int idx = blockIdx.x * blockDim.x + threadIdx.x;
    if (idx >= HH * 4095) return;
    int h = idx / 4095;
    int di = idx % 4095;
    g_biastab[h * 4096 + di] = rel_bias[rel_bucket(di - 2047) * HH + h];
}

// ===========================================================================
// FA2-style attention, bf16x3, KV tile 64 (32 iters), 2 CTAs/SM.
// Block = one (b,h) x 128 q rows; 8 warps: warp w -> q rows [16w,16w+16).
// ALSO materializes out_bias[h][q0:q0+128][:] (b==0 CTAs) from the bias smem
// window — replaces the standalone 537MB bias_write kernel.
// smem: Qh 16K | Ql 16K | 2 x { Kh 8K Kl 8K Vh 8K Vl 8K } | 2 x bias 1K = 98K
// ===========================================================================
#define ASMEM_BYTES (32768 + 2*32768 + 2*1024)

__global__ void __launch_bounds__(256, 2) attn_mma(
    __nv_bfloat16* __restrict__ Ch, __nv_bfloat16* __restrict__ Cl,
    float* __restrict__ out_bias)
{
    extern __shared__ char smem[];
    const uint32_t su = smem_to_u32(smem);
    const int tid = threadIdx.x, l = tid & 31, w = tid >> 5;
    const int grp = l >> 3, lr = l & 7;
    const int bh = blockIdx.y, h = bh & 31, b = bh >> 5;
    const int q0 = blockIdx.x * 128;
    const size_t bhoff = (size_t)bh * SS * HD;
    const int r2 = tid >> 1, hf = tid & 1;

    // Q tiles -> smem (part of group 0)
    {
        const __nv_bfloat16* sh = gq_h + bhoff + (size_t)(q0 + r2) * 64 + hf * 32;
        const __nv_bfloat16* sl = gq_l + bhoff + (size_t)(q0 + r2) * 64 + hf * 32;
        uint32_t dd = (uint32_t)(r2 * 128 + hf * 64);
        #pragma unroll
        for (int i = 0; i < 4; i++) {
            uint32_t o = dd + i * 16; o ^= (o >> 3) & 0x70;
            cp16(su + o,         sh + i * 8);
            cp16(su + 16384 + o, sl + i * 8);
        }
    }

    const float* tabh = g_biastab + h * 4096;
    const int kr = tid >> 2, kq = tid & 3;   // KV loader: row, quarter

    // KV (64 rows) + bias window for ktile kt
    auto issue_kv = [&](int kt) {
        uint32_t sb = su + 32768 + (uint32_t)(kt & 1) * 32768;
        const size_t off = bhoff + (size_t)(kt * 64 + kr) * 64 + kq * 16;
        const uint32_t dd = (uint32_t)(kr * 128 + kq * 32);
        #pragma unroll
        for (int i = 0; i < 2; i++) {
            uint32_t o = dd + i * 16; o ^= (o >> 3) & 0x70;
            cp16(sb + o,         gk_h + off + i * 8);
            cp16(sb + 8192  + o, gk_l + off + i * 8);
            cp16(sb + 16384 + o, gv_h + off + i * 8);
            cp16(sb + 24576 + o, gv_l + off + i * 8);
        }
        int w0 = kt * 64 - q0 + 1920;
        int idx = w0 + tid; if (idx > 4095) idx = 4095;
        cp4(su + 98304 + (uint32_t)(kt & 1) * 1024 + tid * 4, tabh + idx);
    };
    issue_kv(0); CP_COMMIT();
    issue_kv(1); CP_COMMIT();

    float o[8][4];
    #pragma unroll
    for (int nt = 0; nt < 8; nt++)
        #pragma unroll
        for (int i = 0; i < 4; i++) o[nt][i] = 0.f;
    float mrow[2] = {-1e30f, -1e30f};
    float lrow[2] = {0.f, 0.f};

    const uint32_t qbase  = (uint32_t)((w * 16 + lr + (grp & 1) * 8) * 128 + (grp >> 1) * 16);
    const uint32_t kvbase = (uint32_t)((lr + (grp >> 1) * 8) * 128 + (grp & 1) * 16);

    for (int kt = 0; kt < 32; kt++) {
        CP_WAIT(1);
        __syncthreads();
        const uint32_t SB = su + 32768 + (uint32_t)(kt & 1) * 32768;
        const float* bsm = reinterpret_cast<const float*>(smem + 98304 + (kt & 1) * 1024);

        // ---- S = Q K^T (bf16x3), 128q x 64k ----
        float s[8][4];
        #pragma unroll
        for (int j = 0; j < 8; j++)
            #pragma unroll
            for (int i = 0; i < 4; i++) s[j][i] = 0.f;

        #pragma unroll
        for (int ks = 0; ks < 4; ks++) {
            uint32_t qo = qbase + (uint32_t)(ks * 32); qo ^= (qo >> 3) & 0x70;
            uint32_t ah[4], al[4];
            ldx4(ah, su + qo);
            ldx4(al, su + 16384 + qo);
            #pragma unroll
            for (int jj = 0; jj < 4; jj++) {
                uint32_t ko = kvbase + (uint32_t)(jj * 2048 + ks * 32);
                ko ^= (ko >> 3) & 0x70;
                uint32_t kh[4], kl[4];
                ldx4(kh, SB + ko);
                ldx4(kl, SB + 8192 + ko);
                mma_bf16(s[2*jj],   ah, kh[0], kh[1]);
                mma_bf16(s[2*jj],   ah, kl[0], kl[1]);
                mma_bf16(s[2*jj],   al, kh[0], kh[1]);
                mma_bf16(s[2*jj+1], ah, kh[2], kh[3]);
                mma_bf16(s[2*jj+1], ah, kl[2], kl[3]);
                mma_bf16(s[2*jj+1], al, kh[2], kh[3]);
            }
        }

        // ---- bias + online softmax ----
        const int bb = 127 - (w * 16 + (l >> 2)) + 2 * (l & 3);
        #pragma unroll
        for (int j = 0; j < 8; j++) {
            s[j][0] += bsm[bb + 8*j];
            s[j][1] += bsm[bb + 8*j + 1];
            s[j][2] += bsm[bb + 8*j - 8];
            s[j][3] += bsm[bb + 8*j - 7];
        }
        #pragma unroll
        for (int u = 0; u < 2; u++) {
            float mx = -1e30f;
            #pragma unroll
            for (int j = 0; j < 8; j++)
                mx = fmaxf(mx, fmaxf(s[j][2*u], s[j][2*u+1]));
            mx = fmaxf(mx, __shfl_xor_sync(0xffffffffu, mx, 1));
            mx = fmaxf(mx, __shfl_xor_sync(0xffffffffu, mx, 2));
            float mnew = fmaxf(mrow[u], mx);
            float scale = __expf(mrow[u] - mnew);
            mrow[u] = mnew;
            float sum = 0.f;
            #pragma unroll
            for (int j = 0; j < 8; j++) {
                float p0 = __expf(s[j][2*u]   - mnew);
                float p1 = __expf(s[j][2*u+1] - mnew);
                s[j][2*u] = p0; s[j][2*u+1] = p1;
                sum += p0 + p1;
            }
            sum += __shfl_xor_sync(0xffffffffu, sum, 1);
            sum += __shfl_xor_sync(0xffffffffu, sum, 2);
            lrow[u] = lrow[u] * scale + sum;
            #pragma unroll
            for (int nt = 0; nt < 8; nt++) {
                o[nt][2*u]   *= scale;
                o[nt][2*u+1] *= scale;
            }
        }

        // ---- O += P V (bf16x3); P acc fragments reused as A fragments ----
        #pragma unroll
        for (int ks = 0; ks < 4; ks++) {
            uint32_t aph[4], apl[4];
            aph[0] = pack_hi(s[2*ks][0],   s[2*ks][1]);
            aph[1] = pack_hi(s[2*ks][2],   s[2*ks][3]);
            aph[2] = pack_hi(s[2*ks+1][0], s[2*ks+1][1]);
            aph[3] = pack_hi(s[2*ks+1][2], s[2*ks+1][3]);
            apl[0] = pack_lo_res(s[2*ks][0],   s[2*ks][1]);
            apl[1] = pack_lo_res(s[2*ks][2],   s[2*ks][3]);
            apl[2] = pack_lo_res(s[2*ks+1][0], s[2*ks+1][1]);
            apl[3] = pack_lo_res(s[2*ks+1][2], s[2*ks+1][3]);
            #pragma unroll
            for (int dj = 0; dj < 4; dj++) {
                uint32_t vo = kvbase + (uint32_t)(ks * 2048 + dj * 32);
                vo ^= (vo >> 3) & 0x70;
                uint32_t vh[4], vl[4];
                ldx4t(vh, SB + 16384 + vo);
                ldx4t(vl, SB + 24576 + vo);
                mma_bf16(o[2*dj],   aph, vh[0], vh[2]);
                mma_bf16(o[2*dj],   aph, vl[0], vl[2]);
                mma_bf16(o[2*dj],   apl, vh[0], vh[2]);
                mma_bf16(o[2*dj+1], aph, vh[1], vh[3]);
                mma_bf16(o[2*dj+1], aph, vl[1], vl[3]);
                mma_bf16(o[2*dj+1], apl, vh[1], vh[3]);
            }
        }

        // ---- fold in position_bias materialization (b==0 CTAs only) ----
        // out_bias[h][q0+q][kt*64 + kk] = bsm[kk - q + 127]
        if (b == 0) {
            const int q = tid >> 1;
            const int kh2 = (tid & 1) * 32;
            float* dst = out_bias + ((size_t)h * 2048 + (q0 + q)) * 2048
                                  + kt * 64 + kh2;
            const int bidx = kh2 - q + 127;
            #pragma unroll
            for (int i = 0; i < 8; i++) {
                float4 v = make_float4(bsm[bidx + 4*i],     bsm[bidx + 4*i + 1],
                                       bsm[bidx + 4*i + 2], bsm[bidx + 4*i + 3]);
                *reinterpret_cast<float4*>(dst + 4*i) = v;
            }
        }

        __syncthreads();
        if (kt + 2 < 32) issue_kv(kt + 2);
        CP_COMMIT();
    }

    // ---- epilogue: normalize, hi/lo split, store ctx ----
    const float inv0 = 1.f / lrow[0], inv1 = 1.f / lrow[1];
    const int rg0 = b * 2048 + q0 + w * 16 + (l >> 2);
    const size_t base0 = (size_t)rg0 * 2048 + h * 64 + 2 * (l & 3);
    const size_t base1 = base0 + (size_t)8 * 2048;
    #pragma unroll
    for (int nt = 0; nt < 8; nt++) {
        float a0 = o[nt][0] * inv0, a1 = o[nt][1] * inv0;
        float a2 = o[nt][2] * inv1, a3 = o[nt][3] * inv1;
        *reinterpret_cast<uint32_t*>(Ch + base0 + nt * 8) = pack_hi(a0, a1);
        *reinterpret_cast<uint32_t*>(Cl + base0 + nt * 8) = pack_lo_res(a0, a1);
        *reinterpret_cast<uint32_t*>(Ch + base1 + nt * 8) = pack_hi(a2, a3);
        *reinterpret_cast<uint32_t*>(Cl + base1 + nt * 8) = pack_lo_res(a2, a3);
    }
}

// ===========================================================================

extern "C" void kernel_launch(void* const* d_in, const int* in_sizes, int n_in,
                              void* d_out, int out_size)
{
    (void)in_sizes; (void)n_in; (void)out_size;
    const float* x  = (const float*)d_in[0];
    const float* wq = (const float*)d_in[1];
    const float* wk = (const float*)d_in[2];
    const float* wv = (const float*)d_in[3];
    const float* wo = (const float*)d_in[4];
    const float* rb = (const float*)d_in[5];
    float* out      = (float*)d_out;
    float* out_bias = out + (size_t)BB * SS * MD;

    // resolve device-global addresses
    __nv_bfloat16 *xh,*xl,*wqh,*wql,*wkh,*wkl,*wvh,*wvl,*woh,*wol;
    __nv_bfloat16 *qh,*ql,*kh,*kl,*vh,*vl,*ch,*cl;
    cudaGetSymbolAddress((void**)&xh,  gx_h);  cudaGetSymbolAddress((void**)&xl,  gx_l);
    cudaGetSymbolAddress((void**)&wqh, gwq_h); cudaGetSymbolAddress((void**)&wql, gwq_l);
    cudaGetSymbolAddress((void**)&wkh, gwk_h); cudaGetSymbolAddress((void**)&wkl, gwk_l);
    cudaGetSymbolAddress((void**)&wvh, gwv_h); cudaGetSymbolAddress((void**)&wvl, gwv_l);
    cudaGetSymbolAddress((void**)&woh, gwo_h); cudaGetSymbolAddress((void**)&wol, gwo_l);
    cudaGetSymbolAddress((void**)&qh,  gq_h);  cudaGetSymbolAddress((void**)&ql,  gq_l);
    cudaGetSymbolAddress((void**)&kh,  gk_h);  cudaGetSymbolAddress((void**)&kl,  gk_l);
    cudaGetSymbolAddress((void**)&vh,  gv_h);  cudaGetSymbolAddress((void**)&vl,  gv_l);
    cudaGetSymbolAddress((void**)&ch,  gc_h);  cudaGetSymbolAddress((void**)&cl,  gc_l);

    cudaFuncSetAttribute(gemm3<true>,  cudaFuncAttributeMaxDynamicSharedMemorySize, GSMEM_BYTES);
    cudaFuncSetAttribute(gemm3<false>, cudaFuncAttributeMaxDynamicSharedMemorySize, GSMEM_BYTES);
    cudaFuncSetAttribute(attn_mma,     cudaFuncAttributeMaxDynamicSharedMemorySize, ASMEM_BYTES);

    // one-shot conversions + bias table
    convert_kernel<<<(MTOT*MD/4 + 255)/256, 256>>>(x,  xh,  xl,  MTOT*MD/4);
    convert_kernel<<<(MD*MD/4   + 255)/256, 256>>>(wq, wqh, wql, MD*MD/4);
    convert_kernel<<<(MD*MD/4   + 255)/256, 256>>>(wk, wkh, wkl, MD*MD/4);
    convert_kernel<<<(MD*MD/4   + 255)/256, 256>>>(wv, wvh, wvl, MD*MD/4);
    convert_kernel<<<(MD*MD/4   + 255)/256, 256>>>(wo, woh, wol, MD*MD/4);
    bias_table_kernel<<<(HH*4095 + 255)/256, 256>>>(rb);

    // projections -> q/k/v (bf16 hi/lo, [b,h,s,d])
    gemm3<true><<<512, 512, GSMEM_BYTES>>>(xh, xl, wqh, wql, nullptr, qh, ql);
    gemm3<true><<<512, 512, GSMEM_BYTES>>>(xh, xl, wkh, wkl, nullptr, kh, kl);
    gemm3<true><<<512, 512, GSMEM_BYTES>>>(xh, xl, wvh, wvl, nullptr, vh, vl);

    // attention -> ctx (bf16 hi/lo) + position_bias materialization
    attn_mma<<<dim3(16, 64), 256, ASMEM_BYTES>>>(ch, cl, out_bias);

    // output projection (fp32)
    gemm3<false><<<512, 512, GSMEM_BYTES>>>(ch, cl, woh, wol, out, nullptr, nullptr);
}

// round 8
// speedup vs baseline: 1.0229x; 1.0229x over previous
#include <cuda_runtime.h>
#include <cuda_bf16.h>
#include <cstdint>
#include <math.h>

#define BB 2
#define SS 2048
#define HH 32
#define HD 64
#define MD 2048
#define MTOT (BB*SS)

// ---------------- device scratch (static, no allocation) ----------------
__device__ __nv_bfloat16 gx_h[MTOT*MD],  gx_l[MTOT*MD];
__device__ __nv_bfloat16 gwq_h[MD*MD],   gwq_l[MD*MD];
__device__ __nv_bfloat16 gwk_h[MD*MD],   gwk_l[MD*MD];
__device__ __nv_bfloat16 gwv_h[MD*MD],   gwv_l[MD*MD];
__device__ __nv_bfloat16 gwo_h[MD*MD],   gwo_l[MD*MD];
__device__ __nv_bfloat16 gq_h[MTOT*MD],  gq_l[MTOT*MD];   // [bh][s][64]
__device__ __nv_bfloat16 gk_h[MTOT*MD],  gk_l[MTOT*MD];
__device__ __nv_bfloat16 gv_h[MTOT*MD],  gv_l[MTOT*MD];
__device__ __nv_bfloat16 gc_h[MTOT*MD],  gc_l[MTOT*MD];   // ctx [b*S+s][2048]
__device__ float g_biastab[HH*4096];

// ---------------- small helpers ----------------
__device__ __forceinline__ uint32_t smem_to_u32(const void* p) {
    uint32_t a;
    asm("{ .reg .u64 t; cvta.to.shared.u64 t, %1; cvt.u32.u64 %0, t; }" : "=r"(a) : "l"(p));
    return a;
}
__device__ __forceinline__ void cp16(uint32_t dst, const void* src) {
    asm volatile("cp.async.cg.shared.global [%0], [%1], 16;" :: "r"(dst), "l"(src));
}
__device__ __forceinline__ void cp4(uint32_t dst, const void* src) {
    asm volatile("cp.async.ca.shared.global [%0], [%1], 4;" :: "r"(dst), "l"(src));
}
#define CP_COMMIT() asm volatile("cp.async.commit_group;" ::: "memory")
#define CP_WAIT(n)  asm volatile("cp.async.wait_group %0;" :: "n"(n) : "memory")

__device__ __forceinline__ void ldx4(uint32_t* r, uint32_t addr) {
    asm volatile("ldmatrix.sync.aligned.m8n8.x4.shared.b16 {%0,%1,%2,%3}, [%4];"
                 : "=r"(r[0]), "=r"(r[1]), "=r"(r[2]), "=r"(r[3]) : "r"(addr));
}
__device__ __forceinline__ void ldx4t(uint32_t* r, uint32_t addr) {
    asm volatile("ldmatrix.sync.aligned.m8n8.x4.trans.shared.b16 {%0,%1,%2,%3}, [%4];"
                 : "=r"(r[0]), "=r"(r[1]), "=r"(r[2]), "=r"(r[3]) : "r"(addr));
}
__device__ __forceinline__ void mma_bf16(float* d, const uint32_t* a,
                                         uint32_t b0, uint32_t b1) {
    asm volatile(
        "mma.sync.aligned.m16n8k16.row.col.f32.bf16.bf16.f32 "
        "{%0,%1,%2,%3}, {%4,%5,%6,%7}, {%8,%9}, {%0,%1,%2,%3};"
        : "+f"(d[0]), "+f"(d[1]), "+f"(d[2]), "+f"(d[3])
        : "r"(a[0]), "r"(a[1]), "r"(a[2]), "r"(a[3]), "r"(b0), "r"(b1));
}

__device__ __forceinline__ uint32_t pack_hi(float a, float b) {
    return __byte_perm(__float_as_uint(a), __float_as_uint(b), 0x7632);
}
__device__ __forceinline__ uint32_t pack_lo_res(float a, float b) {
    float ra = a - __uint_as_float(__float_as_uint(a) & 0xffff0000u);
    float rb = b - __uint_as_float(__float_as_uint(b) & 0xffff0000u);
    uint32_t r;
    asm("cvt.rn.bf16x2.f32 %0, %1, %2;" : "=r"(r) : "f"(rb), "f"(ra));
    return r;
}

// fp32 -> bf16 hi/lo split (one-shot elementwise)
__global__ void convert_kernel(const float* __restrict__ in,
                               __nv_bfloat16* __restrict__ hi,
                               __nv_bfloat16* __restrict__ lo, int n4) {
    int i = blockIdx.x * blockDim.x + threadIdx.x;
    if (i >= n4) return;
    float4 f = reinterpret_cast<const float4*>(in)[i];
    reinterpret_cast<uint2*>(hi)[i] = make_uint2(pack_hi(f.x, f.y), pack_hi(f.z, f.w));
    reinterpret_cast<uint2*>(lo)[i] = make_uint2(pack_lo_res(f.x, f.y), pack_lo_res(f.z, f.w));
}

// 512-thread GEMM loader: thread t = (row t>>2, quarter t&3), 2x16B per buffer
__device__ __forceinline__ void issue4w(uint32_t sb,
    const __nv_bfloat16* s0, const __nv_bfloat16* s1,
    const __nv_bfloat16* s2, const __nv_bfloat16* s3, int tid)
{
    const int r4 = tid >> 2, qf = tid & 3;
    const uint32_t dd = (uint32_t)(r4 * 128 + qf * 32);
    #pragma unroll
    for (int i = 0; i < 2; i++) {
        uint32_t o = dd + i * 16; o ^= (o >> 3) & 0x70;
        cp16(sb + o,         s0 + i * 8);
        cp16(sb + 16384 + o, s1 + i * 8);
        cp16(sb + 32768 + o, s2 + i * 8);
        cp16(sb + 49152 + o, s3 + i * 8);
    }
}

// 256-thread loader (attention KV): thread t = (row t>>1, half t&1), 4x16B
__device__ __forceinline__ void issue4(uint32_t sb,
    const __nv_bfloat16* s0, const __nv_bfloat16* s1,
    const __nv_bfloat16* s2, const __nv_bfloat16* s3, int tid)
{
    const int r2 = tid >> 1, hf = tid & 1;
    const uint32_t dd = (uint32_t)(r2 * 128 + hf * 64);
    #pragma unroll
    for (int i = 0; i < 4; i++) {
        uint32_t o = dd + i * 16; o ^= (o >> 3) & 0x70;
        cp16(sb + o,         s0 + i * 8);
        cp16(sb + 16384 + o, s1 + i * 8);
        cp16(sb + 32768 + o, s2 + i * 8);
        cp16(sb + 49152 + o, s3 + i * 8);
    }
}

// ===========================================================================
// Shared GEMM mainloop body (bf16x3, 512 threads, 16 warps, 32x32 warp tile,
// 128x128 CTA tile, chunk 64, 3 buffers, issue c+2, WAIT(1)).
// ===========================================================================
#define GSMEM_BYTES (3 * 65536)

struct GemmCtx {
    uint32_t su;
    int tid, l, w, wm, wn, grp, lr;
    uint32_t a_row[2], b_row[2], a_c16, b_c16;
};

__device__ __forceinline__ void gemm_body(
    GemmCtx& g,
    const __nv_bfloat16* pa_h, const __nv_bfloat16* pa_l,
    const __nv_bfloat16* pb_h, const __nv_bfloat16* pb_l,
    float acc[2][4][4])
{
    issue4w(g.su,         pa_h,      pa_l,      pb_h,      pb_l,      g.tid); CP_COMMIT();
    issue4w(g.su + 65536, pa_h + 64, pa_l + 64, pb_h + 64, pb_l + 64, g.tid); CP_COMMIT();

    for (int c = 0; c < 32; c++) {
        CP_WAIT(1);
        __syncthreads();
        if (c + 2 < 32) {
            int k0 = (c + 2) * 64;
            issue4w(g.su + (uint32_t)((c + 2) % 3) * 65536,
                    pa_h + k0, pa_l + k0, pb_h + k0, pb_l + k0, g.tid);
        }
        CP_COMMIT();

        const uint32_t cur = g.su + (uint32_t)(c % 3) * 65536;
        const uint32_t uAh = cur, uAl = cur + 16384,
                       uBh = cur + 32768, uBl = cur + 49152;

        #pragma unroll
        for (int ks = 0; ks < 4; ks++) {
            uint32_t ah[2][4], al[2][4];
            #pragma unroll
            for (int mt = 0; mt < 2; mt++) {
                uint32_t off = g.a_row[mt] + (uint32_t)(ks * 32) + g.a_c16;
                off ^= (off >> 3) & 0x70;
                ldx4(ah[mt], uAh + off);
                ldx4(al[mt], uAl + off);
            }
            uint32_t bh[2][4], bl[2][4];
            #pragma unroll
            for (int j = 0; j < 2; j++) {
                uint32_t off = g.b_row[j] + (uint32_t)(ks * 32) + g.b_c16;
                off ^= (off >> 3) & 0x70;
                ldx4(bh[j], uBh + off);
                ldx4(bl[j], uBl + off);
            }
            #pragma unroll
            for (int mt = 0; mt < 2; mt++) {
                #pragma unroll
                for (int j = 0; j < 2; j++) {
                    mma_bf16(acc[mt][2*j],   ah[mt], bh[j][0], bh[j][1]);
                    mma_bf16(acc[mt][2*j],   ah[mt], bl[j][0], bl[j][1]);
                    mma_bf16(acc[mt][2*j],   al[mt], bh[j][0], bh[j][1]);
                    mma_bf16(acc[mt][2*j+1], ah[mt], bh[j][2], bh[j][3]);
                    mma_bf16(acc[mt][2*j+1], ah[mt], bl[j][2], bl[j][3]);
                    mma_bf16(acc[mt][2*j+1], al[mt], bh[j][2], bh[j][3]);
                }
            }
        }
    }
}

__device__ __forceinline__ void gemm_init(GemmCtx& g, char* smem) {
    g.su = smem_to_u32(smem);
    g.tid = threadIdx.x;
    g.l = g.tid & 31; g.w = g.tid >> 5;
    g.wm = g.w >> 2;  g.wn = g.w & 3;
    g.grp = g.l >> 3; g.lr = g.l & 7;
    #pragma unroll
    for (int mt = 0; mt < 2; mt++)
        g.a_row[mt] = (uint32_t)((g.wm * 32 + mt * 16 + g.lr + (g.grp & 1) * 8) * 128);
    #pragma unroll
    for (int j = 0; j < 2; j++)
        g.b_row[j] = (uint32_t)((g.wn * 32 + j * 16 + g.lr + (g.grp >> 1) * 8) * 128);
    g.a_c16 = (uint32_t)(g.grp >> 1) * 16;
    g.b_c16 = (uint32_t)(g.grp & 1) * 16;
}

// ---- fused QKV: grid 1536 = 3 x 512 tiles (wsel-major), PERM output ----
__global__ void __launch_bounds__(512, 1) gemm_qkv()
{
    extern __shared__ char smem[];
    GemmCtx g; gemm_init(g, smem);

    const int wsel = blockIdx.x >> 9;
    const int tile = blockIdx.x & 511;
    const int m0 = (tile >> 4) * 128, n0 = (tile & 15) * 128;

    const __nv_bfloat16 *Bh, *Bl;
    __nv_bfloat16 *Ch, *Cl;
    if (wsel == 0)      { Bh = gwq_h; Bl = gwq_l; Ch = gq_h; Cl = gq_l; }
    else if (wsel == 1) { Bh = gwk_h; Bl = gwk_l; Ch = gk_h; Cl = gk_l; }
    else                { Bh = gwv_h; Bl = gwv_l; Ch = gv_h; Cl = gv_l; }

    const int r4 = g.tid >> 2, qf = g.tid & 3;
    const __nv_bfloat16* pa_h = gx_h + (size_t)(m0 + r4) * 2048 + qf * 16;
    const __nv_bfloat16* pa_l = gx_l + (size_t)(m0 + r4) * 2048 + qf * 16;
    const __nv_bfloat16* pb_h = Bh   + (size_t)(n0 + r4) * 2048 + qf * 16;
    const __nv_bfloat16* pb_l = Bl   + (size_t)(n0 + r4) * 2048 + qf * 16;

    float acc[2][4][4];
    #pragma unroll
    for (int mt = 0; mt < 2; mt++)
        #pragma unroll
        for (int nt = 0; nt < 4; nt++)
            #pragma unroll
            for (int i = 0; i < 4; i++) acc[mt][nt][i] = 0.f;

    gemm_body(g, pa_h, pa_l, pb_h, pb_l, acc);

    #pragma unroll
    for (int mt = 0; mt < 2; mt++) {
        #pragma unroll
        for (int nt = 0; nt < 4; nt++) {
            int r  = m0 + g.wm * 32 + mt * 16 + (g.l >> 2);
            int cc = n0 + g.wn * 32 + nt * 8 + 2 * (g.l & 3);
            int b = r >> 11, s = r & 2047, h = cc >> 6, d = cc & 63;
            size_t base = (((size_t)(b * 32 + h)) * 2048 + s) * 64 + d;
            *reinterpret_cast<uint32_t*>(Ch + base) =
                pack_hi(acc[mt][nt][0], acc[mt][nt][1]);
            *reinterpret_cast<uint32_t*>(Cl + base) =
                pack_lo_res(acc[mt][nt][0], acc[mt][nt][1]);
            *reinterpret_cast<uint32_t*>(Ch + base + 8 * 64) =
                pack_hi(acc[mt][nt][2], acc[mt][nt][3]);
            *reinterpret_cast<uint32_t*>(Cl + base + 8 * 64) =
                pack_lo_res(acc[mt][nt][2], acc[mt][nt][3]);
        }
    }
}

// ---- output projection: fp32 C, grid 512 ----
__global__ void __launch_bounds__(512, 1) gemm_out(float* __restrict__ Cf)
{
    extern __shared__ char smem[];
    GemmCtx g; gemm_init(g, smem);
    const int m0 = (blockIdx.x >> 4) * 128, n0 = (blockIdx.x & 15) * 128;

    const int r4 = g.tid >> 2, qf = g.tid & 3;
    const __nv_bfloat16* pa_h = gc_h + (size_t)(m0 + r4) * 2048 + qf * 16;
    const __nv_bfloat16* pa_l = gc_l + (size_t)(m0 + r4) * 2048 + qf * 16;
    const __nv_bfloat16* pb_h = gwo_h + (size_t)(n0 + r4) * 2048 + qf * 16;
    const __nv_bfloat16* pb_l = gwo_l + (size_t)(n0 + r4) * 2048 + qf * 16;

    float acc[2][4][4];
    #pragma unroll
    for (int mt = 0; mt < 2; mt++)
        #pragma unroll
        for (int nt = 0; nt < 4; nt++)
            #pragma unroll
            for (int i = 0; i < 4; i++) acc[mt][nt][i] = 0.f;

    gemm_body(g, pa_h, pa_l, pb_h, pb_l, acc);

    #pragma unroll
    for (int mt = 0; mt < 2; mt++) {
        #pragma unroll
        for (int nt = 0; nt < 4; nt++) {
            int r  = m0 + g.wm * 32 + mt * 16 + (g.l >> 2);
            int cc = n0 + g.wn * 32 + nt * 8 + 2 * (g.l & 3);
            *reinterpret_cast<float2*>(Cf + (size_t)r * 2048 + cc) =
                make_float2(acc[mt][nt][0], acc[mt][nt][1]);
            *reinterpret_cast<float2*>(Cf + (size_t)(r + 8) * 2048 + cc) =
                make_float2(acc[mt][nt][2], acc[mt][nt][3]);
        }
    }
}

// ===========================================================================
// relative-position bucket (exact integer T5 formula) + bias table
// ===========================================================================
__device__ __forceinline__ int rel_bucket(int dist) {
    int rel = dist > 0 ? 16 : 0;
    int d = abs(dist);
    int sb;
    if (d < 8)       sb = d;
    else if (d < 12) sb = 8;
    else if (d < 16) sb = 9;
    else if (d < 23) sb = 10;
    else if (d < 32) sb = 11;
    else if (d < 46) sb = 12;
    else if (d < 64) sb = 13;
    else if (d < 91) sb = 14;
    else             sb = 15;
    return rel + sb;
}

__global__ void bias_table_kernel(const float* __restrict__ rel_bias) {
    int idx = blockIdx.x * blockDim.x + threadIdx.x;
    if (idx >= HH * 4095) return;
    int h = idx / 4095;
    int di = idx % 4095;
    g_biastab[h * 4096 + di] = rel_bias[rel_bucket(di - 2047) * HH + h];
}

// ===========================================================================
// FA2-style attention, bf16x3, KV tile 128 (16 iters) — the proven R6 body —
// PLUS folded position_bias materialization (b==0 CTAs, from smem bias window).
// Block = one (b,h) x 128 q rows; 8 warps: warp w -> q rows [16w,16w+16).
// smem: Qh 16K | Ql 16K | 2 x { Kh Kl Vh Vl } 64K | 2 x bias 1K = 162K
// ===========================================================================
#define ASMEM_BYTES (32768 + 2*65536 + 2*1024)

__global__ void __launch_bounds__(256, 1) attn_mma(
    __nv_bfloat16* __restrict__ Ch, __nv_bfloat16* __restrict__ Cl,
    float* __restrict__ out_bias)
{
    extern __shared__ char smem[];
    const uint32_t su = smem_to_u32(smem);
    const int tid = threadIdx.x, l = tid & 31, w = tid >> 5;
    const int grp = l >> 3, lr = l & 7;
    const int bh = blockIdx.y, h = bh & 31, b = bh >> 5;
    const int q0 = blockIdx.x * 128;
    const size_t bhoff = (size_t)bh * SS * HD;
    const int r2 = tid >> 1, hf = tid & 1;

    // Q tiles -> smem (part of group 0)
    {
        const __nv_bfloat16* sh = gq_h + bhoff + (size_t)(q0 + r2) * 64 + hf * 32;
        const __nv_bfloat16* sl = gq_l + bhoff + (size_t)(q0 + r2) * 64 + hf * 32;
        uint32_t dd = (uint32_t)(r2 * 128 + hf * 64);
        #pragma unroll
        for (int i = 0; i < 4; i++) {
            uint32_t o = dd + i * 16; o ^= (o >> 3) & 0x70;
            cp16(su + o,         sh + i * 8);
            cp16(su + 16384 + o, sl + i * 8);
        }
    }

    // KV + bias issue for ktile kt
    auto issue_kv = [&](int kt) {
        uint32_t sb = su + 32768 + (uint32_t)(kt & 1) * 65536;
        size_t off = bhoff + (size_t)(kt * 128 + r2) * 64 + hf * 32;
        issue4(sb, gk_h + off, gk_l + off, gv_h + off, gv_l + off, tid);
        int w0 = kt * 128 - q0 + 1920;
        cp4(su + 163840 + (uint32_t)(kt & 1) * 1024 + tid * 4,
            &g_biastab[h * 4096 + w0 + tid]);
    };
    issue_kv(0); CP_COMMIT();
    issue_kv(1); CP_COMMIT();

    float o[8][4];
    #pragma unroll
    for (int nt = 0; nt < 8; nt++)
        #pragma unroll
        for (int i = 0; i < 4; i++) o[nt][i] = 0.f;
    float mrow[2] = {-1e30f, -1e30f};
    float lrow[2] = {0.f, 0.f};

    const uint32_t qbase  = (uint32_t)((w * 16 + lr + (grp & 1) * 8) * 128 + (grp >> 1) * 16);
    const uint32_t kvbase = (uint32_t)((lr + (grp >> 1) * 8) * 128 + (grp & 1) * 16);

    for (int kt = 0; kt < 16; kt++) {
        CP_WAIT(1);
        __syncthreads();
        const uint32_t SB = su + 32768 + (uint32_t)(kt & 1) * 65536;
        const float* bsm = reinterpret_cast<const float*>(smem + 163840 + (kt & 1) * 1024);

        // ---- S = Q K^T (bf16x3) ----
        float s[16][4];
        #pragma unroll
        for (int j = 0; j < 16; j++)
            #pragma unroll
            for (int i = 0; i < 4; i++) s[j][i] = 0.f;

        #pragma unroll
        for (int ks = 0; ks < 4; ks++) {
            uint32_t qo = qbase + (uint32_t)(ks * 32); qo ^= (qo >> 3) & 0x70;
            uint32_t ah[4], al[4];
            ldx4(ah, su + qo);
            ldx4(al, su + 16384 + qo);
            #pragma unroll
            for (int jj = 0; jj < 8; jj++) {
                uint32_t ko = kvbase + (uint32_t)(jj * 2048 + ks * 32);
                ko ^= (ko >> 3) & 0x70;
                uint32_t kh[4], kl[4];
                ldx4(kh, SB + ko);
                ldx4(kl, SB + 16384 + ko);
                mma_bf16(s[2*jj],   ah, kh[0], kh[1]);
                mma_bf16(s[2*jj],   ah, kl[0], kl[1]);
                mma_bf16(s[2*jj],   al, kh[0], kh[1]);
                mma_bf16(s[2*jj+1], ah, kh[2], kh[3]);
                mma_bf16(s[2*jj+1], ah, kl[2], kl[3]);
                mma_bf16(s[2*jj+1], al, kh[2], kh[3]);
            }
        }

        // ---- bias + online softmax ----
        const int bb = 127 - (w * 16 + (l >> 2)) + 2 * (l & 3);
        #pragma unroll
        for (int j = 0; j < 16; j++) {
            s[j][0] += bsm[bb + 8*j];
            s[j][1] += bsm[bb + 8*j + 1];
            s[j][2] += bsm[bb + 8*j - 8];
            s[j][3] += bsm[bb + 8*j - 7];
        }
        #pragma unroll
        for (int u = 0; u < 2; u++) {
            float mx = -1e30f;
            #pragma unroll
            for (int j = 0; j < 16; j++)
                mx = fmaxf(mx, fmaxf(s[j][2*u], s[j][2*u+1]));
            mx = fmaxf(mx, __shfl_xor_sync(0xffffffffu, mx, 1));
            mx = fmaxf(mx, __shfl_xor_sync(0xffffffffu, mx, 2));
            float mnew = fmaxf(mrow[u], mx);
            float scale = __expf(mrow[u] - mnew);
            mrow[u] = mnew;
            float sum = 0.f;
            #pragma unroll
            for (int j = 0; j < 16; j++) {
                float p0 = __expf(s[j][2*u]   - mnew);
                float p1 = __expf(s[j][2*u+1] - mnew);
                s[j][2*u] = p0; s[j][2*u+1] = p1;
                sum += p0 + p1;
            }
            sum += __shfl_xor_sync(0xffffffffu, sum, 1);
            sum += __shfl_xor_sync(0xffffffffu, sum, 2);
            lrow[u] = lrow[u] * scale + sum;
            #pragma unroll
            for (int nt = 0; nt < 8; nt++) {
                o[nt][2*u]   *= scale;
                o[nt][2*u+1] *= scale;
            }
        }

        // ---- O += P V (bf16x3); P acc fragments reused as A fragments ----
        #pragma unroll
        for (int ks = 0; ks < 8; ks++) {
            uint32_t aph[4], apl[4];
            aph[0] = pack_hi(s[2*ks][0],   s[2*ks][1]);
            aph[1] = pack_hi(s[2*ks][2],   s[2*ks][3]);
            aph[2] = pack_hi(s[2*ks+1][0], s[2*ks+1][1]);
            aph[3] = pack_hi(s[2*ks+1][2], s[2*ks+1][3]);
            apl[0] = pack_lo_res(s[2*ks][0],   s[2*ks][1]);
            apl[1] = pack_lo_res(s[2*ks][2],   s[2*ks][3]);
            apl[2] = pack_lo_res(s[2*ks+1][0], s[2*ks+1][1]);
            apl[3] = pack_lo_res(s[2*ks+1][2], s[2*ks+1][3]);
            #pragma unroll
            for (int dj = 0; dj < 4; dj++) {
                uint32_t vo = kvbase + (uint32_t)(ks * 2048 + dj * 32);
                vo ^= (vo >> 3) & 0x70;
                uint32_t vh[4], vl[4];
                ldx4t(vh, SB + 32768 + vo);
                ldx4t(vl, SB + 49152 + vo);
                mma_bf16(o[2*dj],   aph, vh[0], vh[2]);
                mma_bf16(o[2*dj],   aph, vl[0], vl[2]);
                mma_bf16(o[2*dj],   apl, vh[0], vh[2]);
                mma_bf16(o[2*dj+1], aph, vh[1], vh[3]);
                mma_bf16(o[2*dj+1], aph, vl[1], vl[3]);
                mma_bf16(o[2*dj+1], apl, vh[1], vh[3]);
            }
        }

        // ---- fold in position_bias materialization (b==0 CTAs only) ----
        // out_bias[h][q0+q][kt*128 + kk] = bsm[kk - q + 127]
        if (b == 0) {
            const int q = tid >> 1;          // 0..127
            const int kh2 = (tid & 1) * 64;  // 0 or 64
            float* dst = out_bias + ((size_t)h * 2048 + (q0 + q)) * 2048
                                  + kt * 128 + kh2;
            const int bidx = kh2 - q + 127;
            #pragma unroll
            for (int i = 0; i < 16; i++) {
                *reinterpret_cast<float4*>(dst + 4*i) =
                    make_float4(bsm[bidx + 4*i],     bsm[bidx + 4*i + 1],
                                bsm[bidx + 4*i + 2], bsm[bidx + 4*i + 3]);
            }
        }

        __syncthreads();
        if (kt + 2 < 16) issue_kv(kt + 2);
        CP_COMMIT();
    }

    // ---- epilogue: normalize, hi/lo split, store ctx ----
    const float inv0 = 1.f / lrow[0], inv1 = 1.f / lrow[1];
    const int rg0 = b * 2048 + q0 + w * 16 + (l >> 2);
    const size_t base0 = (size_t)rg0 * 2048 + h * 64 + 2 * (l & 3);
    const size_t base1 = base0 + (size_t)8 * 2048;
    #pragma unroll
    for (int nt = 0; nt < 8; nt++) {
        float a0 = o[nt][0] * inv0, a1 = o[nt][1] * inv0;
        float a2 = o[nt][2] * inv1, a3 = o[nt][3] * inv1;
        *reinterpret_cast<uint32_t*>(Ch + base0 + nt * 8) = pack_hi(a0, a1);
        *reinterpret_cast<uint32_t*>(Cl + base0 + nt * 8) = pack_lo_res(a0, a1);
        *reinterpret_cast<uint32_t*>(Ch + base1 + nt * 8) = pack_hi(a2, a3);
        *reinterpret_cast<uint32_t*>(Cl + base1 + nt * 8) = pack_lo_res(a2, a3);
    }
}

// ===========================================================================

extern "C" void kernel_launch(void* const* d_in, const int* in_sizes, int n_in,
                              void* d_out, int out_size)
{
    (void)in_sizes; (void)n_in; (void)out_size;
    const float* x  = (const float*)d_in[0];
    const float* wq = (const float*)d_in[1];
    const float* wk = (const float*)d_in[2];
    const float* wv = (const float*)d_in[3];
    const float* wo = (const float*)d_in[4];
    const float* rb = (const float*)d_in[5];
    float* out      = (float*)d_out;
    float* out_bias = out + (size_t)BB * SS * MD;

    // resolve device-global addresses (conversion targets)
    __nv_bfloat16 *xh,*xl,*wqh,*wql,*wkh,*wkl,*wvh,*wvl,*woh,*wol,*ch,*cl;
    cudaGetSymbolAddress((void**)&xh,  gx_h);  cudaGetSymbolAddress((void**)&xl,  gx_l);
    cudaGetSymbolAddress((void**)&wqh, gwq_h); cudaGetSymbolAddress((void**)&wql, gwq_l);
    cudaGetSymbolAddress((void**)&wkh, gwk_h); cudaGetSymbolAddress((void**)&wkl, gwk_l);
    cudaGetSymbolAddress((void**)&wvh, gwv_h); cudaGetSymbolAddress((void**)&wvl, gwv_l);
    cudaGetSymbolAddress((void**)&woh, gwo_h); cudaGetSymbolAddress((void**)&wol, gwo_l);
    cudaGetSymbolAddress((void**)&ch,  gc_h);  cudaGetSymbolAddress((void**)&cl,  gc_l);

    cudaFuncSetAttribute(gemm_qkv, cudaFuncAttributeMaxDynamicSharedMemorySize, GSMEM_BYTES);
    cudaFuncSetAttribute(gemm_out, cudaFuncAttributeMaxDynamicSharedMemorySize, GSMEM_BYTES);
    cudaFuncSetAttribute(attn_mma, cudaFuncAttributeMaxDynamicSharedMemorySize, ASMEM_BYTES);

    // one-shot conversions + bias table
    convert_kernel<<<(MTOT*MD/4 + 255)/256, 256>>>(x,  xh,  xl,  MTOT*MD/4);
    convert_kernel<<<(MD*MD/4   + 255)/256, 256>>>(wq, wqh, wql, MD*MD/4);
    convert_kernel<<<(MD*MD/4   + 255)/256, 256>>>(wk, wkh, wkl, MD*MD/4);
    convert_kernel<<<(MD*MD/4   + 255)/256, 256>>>(wv, wvh, wvl, MD*MD/4);
    convert_kernel<<<(MD*MD/4   + 255)/256, 256>>>(wo, woh, wol, MD*MD/4);
    bias_table_kernel<<<(HH*4095 + 255)/256, 256>>>(rb);

    // fused QKV projections -> q/k/v (bf16 hi/lo, [b,h,s,d]) in ONE launch
    gemm_qkv<<<1536, 512, GSMEM_BYTES>>>();

    // attention -> ctx (bf16 hi/lo) + position_bias materialization
    attn_mma<<<dim3(16, 64), 256, ASMEM_BYTES>>>(ch, cl, out_bias);

    // output projection (fp32)
    gemm_out<<<512, 512, GSMEM_BYTES>>>(out);
}